// round 1
// baseline (speedup 1.0000x reference)
#include <cuda_runtime.h>

// Problem constants (from reference: SLEN=208, PTILE=8, STEP=2, EDGE=3, MAXDET=2)
#define BATCH 16
#define NSRC  100
#define NFLUX 5
#define NT    101                 // tiles per dim
#define PT    (NT * NT)           // 10201 tiles per batch
#define BP    (BATCH * PT)        // 163216
// Output sections, concatenated flat (float32):
//   n_sources [BP], locs [BP*2*2], fluxes [BP*2*5], is_on [BP*2]
#define OFF_L (BP)
#define OFF_F (OFF_L + BP * 4)
#define OFF_I (OFF_F + BP * 10)

// ---------------------------------------------------------------------------
// Kernel 1: zero the whole output (defaults: n=0, locs=0, fluxes=0, is_on=0)
// ---------------------------------------------------------------------------
__global__ void zero_fill_kernel(float4* __restrict__ out4, int nvec,
                                 float* __restrict__ out, int ntail_start, int ntotal) {
    int i = blockIdx.x * blockDim.x + threadIdx.x;
    if (i < nvec) out4[i] = make_float4(0.f, 0.f, 0.f, 0.f);
    // tail (out_size % 4), handled by first few threads of block 0
    if (blockIdx.x == 0 && threadIdx.x < 4) {
        int t = ntail_start + threadIdx.x;
        if (t < ntotal) out[t] = 0.f;
    }
}

// ---------------------------------------------------------------------------
// Kernel 2: per-source scatter. Each source maps to at most ONE tile:
//   interval per dim is (2k+2.5, 2k+4.5), disjoint across k.
// Rank among same-tile sources (by source index, matching jax stable argsort)
// decides the MAXDET=2 slot.
// ---------------------------------------------------------------------------
__global__ void scatter_kernel(const float* __restrict__ locs,
                               const float* __restrict__ fluxes,
                               float* __restrict__ out) {
    __shared__ int stile[NSRC];
    const int b = blockIdx.x;
    const int s = threadIdx.x;

    int   mytile = -1;
    float fx = 0.f, fy = 0.f;

    if (s < NSRC) {
        // locs: (B, S, 2) row-major
        float p0 = locs[(b * NSRC + s) * 2 + 0] * 207.0f;   // SLEN-1
        float p1 = locs[(b * NSRC + s) * 2 + 1] * 207.0f;
        int kx = (int)floorf((p0 - 2.5f) * 0.5f);
        int ky = (int)floorf((p1 - 2.5f) * 0.5f);
        float lx = 2.0f * (float)kx + 2.5f;                 // left edge (exact fp32)
        float ly = 2.0f * (float)ky + 2.5f;
        bool v0 = (kx >= 0) && (kx < NT) && (p0 > lx) && (p0 < lx + 2.0f) && (p0 != 0.0f);
        bool v1 = (ky >= 0) && (ky < NT) && (p1 > ly) && (p1 < ly + 2.0f) && (p1 != 0.0f);
        if (v0 && v1) {
            mytile = kx * NT + ky;
            fx = (p0 - lx) * 0.5f;                          // (lp - left) / scale, exact
            fy = (p1 - ly) * 0.5f;
        }
        stile[s] = mytile;
    }
    __syncthreads();

    if (s < NSRC && mytile >= 0) {
        int count = 0, rank = 0;
        #pragma unroll
        for (int j = 0; j < NSRC; j++) {
            int t = stile[j];
            if (t == mytile) {
                count++;
                if (j < s) rank++;
            }
        }
        int g = b * PT + mytile;
        if (rank == 0) {
            out[g] = (float)(count < 2 ? count : 2);        // min(n, MAXDET)
        }
        if (rank < 2) {
            out[OFF_L + g * 4 + rank * 2 + 0] = fx;
            out[OFF_L + g * 4 + rank * 2 + 1] = fy;
            const float* fl = fluxes + (b * NSRC + s) * NFLUX;
            #pragma unroll
            for (int j = 0; j < NFLUX; j++)
                out[OFF_F + g * 10 + rank * 5 + j] = fl[j];
            out[OFF_I + g * 2 + rank] = 1.0f;
        }
    }
}

extern "C" void kernel_launch(void* const* d_in, const int* in_sizes, int n_in,
                              void* d_out, int out_size) {
    const float* locs   = (const float*)d_in[0];   // (16, 100, 2) f32
    const float* fluxes = (const float*)d_in[1];   // (16, 100, 5) f32
    float* out = (float*)d_out;

    int nvec = out_size / 4;                       // float4 count
    int blocks = (nvec + 255) / 256;
    zero_fill_kernel<<<blocks, 256>>>((float4*)out, nvec, out, nvec * 4, out_size);
    scatter_kernel<<<BATCH, 128>>>(locs, fluxes, out);
}